// round 4
// baseline (speedup 1.0000x reference)
#include <cuda_runtime.h>
#include <math.h>

#define NN    10000
#define HH    4
#define FF    128
#define HF    (HH*FF)      // 512
#define EE    320000
#define ET    (EE+NN)      // 330000 edges incl self-loops
#define SLOPE 0.2f

// ---------------- scratch (device globals; no allocation allowed) ----------
__device__ float g_hp  [(size_t)NN*HF];   // projected features [N,H,F]
__device__ float g_acc [(size_t)NN*HF];   // aggregation accumulator [N,H,F]
__device__ float g_x   [(size_t)NN*FF];   // inter-layer features [N,F]
__device__ float g_z   [(size_t)NN*FF];   // encoder output z [N,F]
__device__ float g_zt  [(size_t)FF*NN];   // z transposed [F,N]
__device__ float g_als [NN*HH];
__device__ float g_ald [NN*HH];
__device__ float g_m   [NN*HH];
__device__ float g_s   [NN*HH];
__device__ float g_eval[(size_t)ET*HH];
__device__ int   g_is64;                  // edge_index dtype flag

// --------- edge-index dtype sniffer ----------------------------------------
// int64 little-endian: every odd 32-bit word of the buffer is 0.
// int32: odd words are random node ids (virtually never all zero).
__global__ void detect_ei_kernel(const int* __restrict__ ei32)
{
    __shared__ int any;
    if (threadIdx.x == 0) any = 0;
    __syncthreads();
    for (int i = threadIdx.x; i < 4096; i += blockDim.x)
        if (ei32[2 * i + 1] != 0) atomicOr(&any, 1);
    __syncthreads();
    if (threadIdx.x == 0) g_is64 = (any == 0);
}

__device__ __forceinline__ void edge_sd(const int* __restrict__ ei32, int e,
                                        int& s, int& d)
{
    if (e >= EE) { s = d = e - EE; return; }          // self-loop
    if (g_is64) { s = ei32[2 * e]; d = ei32[2 * (EE + e)]; }
    else        { s = ei32[e];     d = ei32[EE + e]; }
}

__device__ __forceinline__ bool valid_nd(int s, int d)
{
    return ((unsigned)s < NN) && ((unsigned)d < NN);
}

// ---------------- SGEMM 128x128x8, 256 thr, 8x8 microtile -------------------
// C[M,N] = A[M,K] @ B[K,N], row-major. ACT: 0=none, 1=sigmoid
template<int ACT>
__global__ void sgemm128(int M, int N, int K,
                         const float* __restrict__ A,
                         const float* __restrict__ B,
                         float* __restrict__ C)
{
    __shared__ float As[8][128];
    __shared__ float Bs[8][128];

    const int tid = threadIdx.x;
    const int tx  = tid & 15;          // N dir
    const int ty  = tid >> 4;          // M dir
    const int rowBase = blockIdx.y * 128;
    const int colBase = blockIdx.x * 128;

    const int aRow = tid >> 1;         // 0..127
    const int aCol = (tid & 1) * 4;    // 0 or 4
    const int bRow = tid >> 5;         // 0..7
    const int bCol = (tid & 31) * 4;   // 0..124

    float acc[8][8];
    #pragma unroll
    for (int i = 0; i < 8; i++)
        #pragma unroll
        for (int j = 0; j < 8; j++) acc[i][j] = 0.f;

    const int ar = rowBase + aRow;
    const int bc = colBase + bCol;

    for (int k0 = 0; k0 < K; k0 += 8) {
        float4 av = make_float4(0.f, 0.f, 0.f, 0.f);
        if (ar < M)
            av = *reinterpret_cast<const float4*>(&A[(size_t)ar * K + k0 + aCol]);
        As[aCol + 0][aRow] = av.x;
        As[aCol + 1][aRow] = av.y;
        As[aCol + 2][aRow] = av.z;
        As[aCol + 3][aRow] = av.w;

        float4 bv = make_float4(0.f, 0.f, 0.f, 0.f);
        if (bc < N)
            bv = *reinterpret_cast<const float4*>(&B[(size_t)(k0 + bRow) * N + bc]);
        *reinterpret_cast<float4*>(&Bs[bRow][bCol]) = bv;

        __syncthreads();

        #pragma unroll
        for (int k = 0; k < 8; k++) {
            float ra[8], rb[8];
            #pragma unroll
            for (int i = 0; i < 8; i++) ra[i] = As[k][ty * 8 + i];
            #pragma unroll
            for (int j = 0; j < 8; j++) rb[j] = Bs[k][tx * 8 + j];
            #pragma unroll
            for (int i = 0; i < 8; i++)
                #pragma unroll
                for (int j = 0; j < 8; j++)
                    acc[i][j] = fmaf(ra[i], rb[j], acc[i][j]);
        }
        __syncthreads();
    }

    #pragma unroll
    for (int i = 0; i < 8; i++) {
        const int row = rowBase + ty * 8 + i;
        if (row >= M) continue;
        #pragma unroll
        for (int j = 0; j < 8; j++) {
            const int col = colBase + tx * 8 + j;
            if (col >= N) continue;
            float v = acc[i][j];
            if (ACT == 1) v = 1.f / (1.f + __expf(-v));
            C[(size_t)row * N + col] = v;
        }
    }
}

// --------- per-node attention logits: als/ald[n,h] = <h[n,h,:], a[h,:]> -----
__global__ void attn_logits_kernel(const float* __restrict__ hp,
                                   const float* __restrict__ a_src,
                                   const float* __restrict__ a_dst)
{
    const int warp = (blockIdx.x * blockDim.x + threadIdx.x) >> 5;
    const int lane = threadIdx.x & 31;
    if (warp >= NN * HH) return;
    const int n = warp / HH, h = warp % HH;
    const float* hv = hp + (size_t)n * HF + h * FF;
    float s1 = 0.f, s2 = 0.f;
    #pragma unroll
    for (int j = 0; j < 4; j++) {
        const int f = lane + 32 * j;
        const float v = hv[f];
        s1 = fmaf(v, a_src[h * FF + f], s1);
        s2 = fmaf(v, a_dst[h * FF + f], s2);
    }
    #pragma unroll
    for (int o = 16; o; o >>= 1) {
        s1 += __shfl_xor_sync(0xffffffffu, s1, o);
        s2 += __shfl_xor_sync(0xffffffffu, s2, o);
    }
    if (lane == 0) { g_als[warp] = s1; g_ald[warp] = s2; }
}

// --------- init m=-inf, s=0, acc=0 -----------------------------------------
__global__ void init_kernel()
{
    const size_t total = (size_t)NN * HF;
    for (size_t i = blockIdx.x * blockDim.x + threadIdx.x; i < total;
         i += (size_t)gridDim.x * blockDim.x) {
        g_acc[i] = 0.f;
        if (i < NN * HH) { g_m[i] = -INFINITY; g_s[i] = 0.f; }
    }
}

__device__ __forceinline__ void atomicMaxFloat(float* addr, float val)
{
    if (val >= 0.f) atomicMax((int*)addr, __float_as_int(val));
    else            atomicMin((unsigned int*)addr, __float_as_uint(val));
}

// --------- edge pass 1: leaky-relu logits + segment max ---------------------
__global__ void edge_logits_kernel(const int* __restrict__ ei)
{
    const int idx = blockIdx.x * blockDim.x + threadIdx.x;
    if (idx >= ET * HH) return;
    const int e = idx >> 2, h = idx & 3;
    int s, d; edge_sd(ei, e, s, d);
    if (!valid_nd(s, d)) { g_eval[idx] = -INFINITY; return; }
    float v = g_als[s * HH + h] + g_ald[d * HH + h];
    v = v > 0.f ? v : SLOPE * v;
    g_eval[idx] = v;
    atomicMaxFloat(&g_m[d * HH + h], v);
}

// --------- edge pass 2: exp + segment sum -----------------------------------
__global__ void edge_exp_kernel(const int* __restrict__ ei)
{
    const int idx = blockIdx.x * blockDim.x + threadIdx.x;
    if (idx >= ET * HH) return;
    const int e = idx >> 2, h = idx & 3;
    int s, d; edge_sd(ei, e, s, d);
    if (!valid_nd(s, d)) { g_eval[idx] = 0.f; return; }
    const float v = expf(g_eval[idx] - g_m[d * HH + h]);
    g_eval[idx] = v;
    atomicAdd(&g_s[d * HH + h], v);
}

// --------- edge pass 3: scatter messages (warp per (edge,head)) -------------
__global__ void edge_msg_kernel(const int* __restrict__ ei)
{
    const int warp = (blockIdx.x * blockDim.x + threadIdx.x) >> 5;
    const int lane = threadIdx.x & 31;
    if (warp >= ET * HH) return;
    const int e = warp >> 2, h = warp & 3;
    int s, d; edge_sd(ei, e, s, d);
    if (!valid_nd(s, d)) return;
    const float alpha = g_eval[warp] / g_s[d * HH + h];
    const float4 hv = *reinterpret_cast<const float4*>(
        &g_hp[(size_t)s * HF + h * FF + lane * 4]);
    float* ap = &g_acc[(size_t)d * HF + h * FF + lane * 4];
    atomicAdd(ap + 0, hv.x * alpha);
    atomicAdd(ap + 1, hv.y * alpha);
    atomicAdd(ap + 2, hv.z * alpha);
    atomicAdd(ap + 3, hv.w * alpha);
}

// --------- finalize: head mean + bias + activation --------------------------
// act: 0 = relu, 1 = tanh.  Optional mirror store to `mirror` (may be null).
__global__ void finalize_kernel(const float* __restrict__ b, float* __restrict__ out,
                                int act, float* __restrict__ mirror)
{
    const int idx = blockIdx.x * blockDim.x + threadIdx.x;
    if (idx >= NN * FF) return;
    const int n = idx / FF, f = idx % FF;
    const float* a = &g_acc[(size_t)n * HF];
    float v = (a[f] + a[FF + f] + a[2 * FF + f] + a[3 * FF + f]) * 0.25f + b[f];
    v = act == 0 ? fmaxf(v, 0.f) : tanhf(v);
    out[(size_t)n * FF + f] = v;
    if (mirror) mirror[(size_t)n * FF + f] = v;
}

__global__ void transpose_z_kernel(const float* __restrict__ z, float* __restrict__ zt)
{
    const int idx = blockIdx.x * blockDim.x + threadIdx.x;
    if (idx >= NN * FF) return;
    const int n = idx / FF, f = idx % FF;
    zt[(size_t)f * NN + n] = z[idx];
}

// ---------------------------------------------------------------------------
static void run_layer(const float* x, int Din, const float* W,
                      const float* a_s, const float* a_d, const float* b,
                      const int* ei, float* hp, float* out, int act,
                      float* mirror)
{
    {
        dim3 grid((HF + 127) / 128, (NN + 127) / 128);
        sgemm128<0><<<grid, 256>>>(NN, HF, Din, x, W, hp);
    }
    attn_logits_kernel<<<(NN * HH * 32 + 255) / 256, 256>>>(hp, a_s, a_d);
    init_kernel<<<1024, 256>>>();
    edge_logits_kernel<<<(ET * HH + 255) / 256, 256>>>(ei);
    edge_exp_kernel   <<<(ET * HH + 255) / 256, 256>>>(ei);
    edge_msg_kernel   <<<(ET * HH * 32 + 255) / 256, 256>>>(ei);
    finalize_kernel<<<(NN * FF + 255) / 256, 256>>>(b, out, act, mirror);
}

extern "C" void kernel_launch(void* const* d_in, const int* in_sizes, int n_in,
                              void* d_out, int out_size)
{
    // ---- size-based input classification (robust to metadata ordering) ----
    const int SZ_X  = NN * NN;      // 100,000,000
    const int SZ_EI = 2 * EE;       // 640,000
    const int SZ_W0 = NN * HF;      // 5,120,000
    const int SZ_W  = FF * HF;      // 65,536
    const int SZ_A  = HH * FF;      // 512
    const int SZ_B  = FF;           // 128

    const float* x  = nullptr;
    const int*   ei = nullptr;
    const float* W [4] = {nullptr, nullptr, nullptr, nullptr};
    const float* AS[4] = {nullptr, nullptr, nullptr, nullptr};
    const float* AD[4] = {nullptr, nullptr, nullptr, nullptr};
    const float* B [4] = {nullptr, nullptr, nullptr, nullptr};

    int wIdx = 1, bIdx = 0;
    int aPos[8]; const float* aPtr[8]; int nA = 0;

    for (int i = 0; i < n_in; i++) {
        const int s = in_sizes[i];
        if      (s == SZ_X)  x = (const float*)d_in[i];
        else if (s == SZ_EI) ei = (const int*)d_in[i];
        else if (s == SZ_W0) W[0] = (const float*)d_in[i];
        else if (s == SZ_W)  { if (wIdx < 4) W[wIdx++] = (const float*)d_in[i]; }
        else if (s == SZ_A)  { if (nA < 8) { aPos[nA] = i; aPtr[nA] = (const float*)d_in[i]; nA++; } }
        else if (s == SZ_B)  { if (bIdx < 4) B[bIdx++] = (const float*)d_in[i]; }
    }

    // Disambiguate the eight [H,F] attention vectors:
    //  - signature order: W0..W3, as0..3, ad0..3, b0..3 -> contiguous block of 8
    //  - dict order:      ... W_i, as_i, ad_i, b_i ...  -> adjacent pairs with gaps
    bool contiguous8 = (nA == 8);
    for (int i = 1; i < nA; i++)
        if (aPos[i] != aPos[0] + i) { contiguous8 = false; break; }

    if (contiguous8) {
        for (int i = 0; i < 4; i++) { AS[i] = aPtr[i]; AD[i] = aPtr[4 + i]; }
    } else {
        for (int i = 0; i < 4; i++) { AS[i] = aPtr[2 * i]; AD[i] = aPtr[2 * i + 1]; }
    }

    float* hp;  cudaGetSymbolAddress((void**)&hp,  g_hp);
    float* xbuf;cudaGetSymbolAddress((void**)&xbuf,g_x);
    float* zbuf;cudaGetSymbolAddress((void**)&zbuf,g_z);
    float* zt;  cudaGetSymbolAddress((void**)&zt,  g_zt);

    float* out = (float*)d_out;                     // adj_recon [N,N]
    const long long need = (long long)NN * NN + (long long)NN * FF;
    float* zmirror = ((long long)out_size >= need) ? out + (size_t)NN * NN : nullptr;

    // edge_index dtype detection (int32 vs int64), device-side, capture-safe
    detect_ei_kernel<<<1, 256>>>(ei);

    run_layer(x,    NN, W[0], AS[0], AD[0], B[0], ei, hp, xbuf, 0, nullptr);
    run_layer(xbuf, FF, W[1], AS[1], AD[1], B[1], ei, hp, xbuf, 0, nullptr);
    run_layer(xbuf, FF, W[2], AS[2], AD[2], B[2], ei, hp, xbuf, 0, nullptr);
    run_layer(xbuf, FF, W[3], AS[3], AD[3], B[3], ei, hp, zbuf, 1, zmirror);

    // decode: adj = sigmoid(z @ z^T)
    transpose_z_kernel<<<(NN * FF + 255) / 256, 256>>>(zbuf, zt);
    {
        dim3 grid((NN + 127) / 128, (NN + 127) / 128);
        sgemm128<1><<<grid, 256>>>(NN, NN, FF, zbuf, zt, out);
    }
}